// round 1
// baseline (speedup 1.0000x reference)
#include <cuda_runtime.h>

// ---------------------------------------------------------------------------
// SSIM 3D, separable 11-tap Gaussian (sigma=1.5), VALID padding.
// Input: img1, img2 float32 (2,1,192,192,192). Output: scalar mean SSIM.
// 3-pass separable conv over 5 fused fields + SSIM map + deterministic mean.
// ---------------------------------------------------------------------------

#define WSZ 11
static const int IN_D = 192;
static const int ON_D = 182;   // 192 - 11 + 1

// Gaussian window, normalized (precomputed, matches reference to ~1e-7)
__constant__ float c_g[WSZ] = {
    0.0010283817f, 0.0075987700f, 0.0360007700f, 0.1093607000f,
    0.2130055500f, 0.2660117200f,
    0.2130055500f, 0.1093607000f, 0.0360007700f, 0.0075987700f,
    0.0010283817f
};

// Scratch (static device globals; no runtime allocation allowed)
// s1: [5 fields][2 n][192 d][192 h][182 w]
// s2: [5 fields][2 n][192 d][182 oh][182 ow]
static const size_t FS1 = (size_t)2 * 192 * 192 * 182;   // per-field size pass1
static const size_t FS2 = (size_t)2 * 192 * 182 * 182;   // per-field size pass2
__device__ float d_s1[5 * FS1];
__device__ float d_s2[5 * FS2];

__device__ unsigned d_minbits;
__device__ unsigned d_maxbits;
__device__ float    d_c1c2[2];
__device__ float    d_bsum[3623];

// ---------------------------------------------------------------------------

__global__ void init_kernel() {
    d_minbits = 0xFFFFFFFFu;
    d_maxbits = 0u;
}

__device__ __forceinline__ unsigned f2mono(float f) {
    unsigned u = __float_as_uint(f);
    return (u & 0x80000000u) ? ~u : (u | 0x80000000u);
}
__device__ __forceinline__ float mono2f(unsigned u) {
    return (u & 0x80000000u) ? __uint_as_float(u ^ 0x80000000u)
                             : __uint_as_float(~u);
}

__global__ void minmax_kernel(const float* __restrict__ img1, size_t n) {
    unsigned lmin = 0xFFFFFFFFu, lmax = 0u;
    size_t stride = (size_t)gridDim.x * blockDim.x;
    for (size_t i = (size_t)blockIdx.x * blockDim.x + threadIdx.x; i < n; i += stride) {
        unsigned u = f2mono(img1[i]);
        lmin = min(lmin, u);
        lmax = max(lmax, u);
    }
    // warp reduce
    #pragma unroll
    for (int off = 16; off; off >>= 1) {
        lmin = min(lmin, __shfl_down_sync(0xFFFFFFFFu, lmin, off));
        lmax = max(lmax, __shfl_down_sync(0xFFFFFFFFu, lmax, off));
    }
    __shared__ unsigned smin[8], smax[8];
    int wid = threadIdx.x >> 5, lane = threadIdx.x & 31;
    if (lane == 0) { smin[wid] = lmin; smax[wid] = lmax; }
    __syncthreads();
    if (threadIdx.x < 8) {
        lmin = smin[threadIdx.x];
        lmax = smax[threadIdx.x];
        #pragma unroll
        for (int off = 4; off; off >>= 1) {
            lmin = min(lmin, __shfl_down_sync(0xFFu, lmin, off));
            lmax = max(lmax, __shfl_down_sync(0xFFu, lmax, off));
        }
        if (threadIdx.x == 0) {
            atomicMin(&d_minbits, lmin);
            atomicMax(&d_maxbits, lmax);
        }
    }
}

__global__ void const_kernel() {
    float mx = mono2f(d_maxbits);
    float mn = mono2f(d_minbits);
    float max_val = (mx > 128.0f) ? 255.0f : 1.0f;
    float min_val = (mn < -0.5f) ? -1.0f : 0.0f;
    float L = max_val - min_val;
    float c1 = 0.01f * L, c2 = 0.03f * L;
    d_c1c2[0] = c1 * c1;
    d_c1c2[1] = c2 * c2;
}

// ---------------------------------------------------------------------------
// Pass 1: conv along W (contiguous), fused with the 5 pointwise products.
// One block per (n,d,h) row. 192 threads; threads 0..181 produce outputs.
// ---------------------------------------------------------------------------
__global__ void __launch_bounds__(192) pass1_kernel(
    const float* __restrict__ img1, const float* __restrict__ img2) {
    __shared__ float sx[192];
    __shared__ float sy[192];
    int row = blockIdx.x;                  // (n*192 + d)*192 + h
    size_t base = (size_t)row * 192;
    int t = threadIdx.x;
    sx[t] = img1[base + t];
    sy[t] = img2[base + t];
    __syncthreads();
    if (t < 182) {
        float a0 = 0.f, a1 = 0.f, a2 = 0.f, a3 = 0.f, a4 = 0.f;
        #pragma unroll
        for (int k = 0; k < WSZ; k++) {
            float g = c_g[k];
            float a = sx[t + k], b = sy[t + k];
            float ta = g * a, tb = g * b;
            a0 += ta;
            a1 += tb;
            a2 += ta * a;
            a3 += tb * b;
            a4 += ta * b;
        }
        size_t ob = (size_t)row * 182 + t;
        d_s1[ob]           = a0;
        d_s1[FS1 + ob]     = a1;
        d_s1[2 * FS1 + ob] = a2;
        d_s1[3 * FS1 + ob] = a3;
        d_s1[4 * FS1 + ob] = a4;
    }
}

// ---------------------------------------------------------------------------
// Pass 2: conv along H. Each thread computes a strip of 13 outputs (182=14*13)
// at fixed (field, n, d, ow). 23 loads -> 13 outputs (scatter form, unrolled).
// ---------------------------------------------------------------------------
__global__ void __launch_bounds__(256) pass2_kernel() {
    const size_t TOT = (size_t)5 * 2 * 192 * 14 * 182;
    size_t idx = (size_t)blockIdx.x * blockDim.x + threadIdx.x;
    if (idx >= TOT) return;
    int ow = (int)(idx % 182); size_t t = idx / 182;
    int strip = (int)(t % 14);
    int plane = (int)(t / 14);             // (f*2+n)*192 + d, 0..1919
    int h0 = strip * 13;

    const float* __restrict__ src = d_s1 + (size_t)plane * (192 * 182);
    float acc[13];
    #pragma unroll
    for (int o = 0; o < 13; o++) acc[o] = 0.f;

    #pragma unroll
    for (int j = 0; j < 23; j++) {
        float v = src[(size_t)(h0 + j) * 182 + ow];
        #pragma unroll
        for (int o = 0; o < 13; o++) {
            int k = j - o;
            if (k >= 0 && k < WSZ) acc[o] += c_g[k] * v;
        }
    }
    float* dst = d_s2 + (size_t)plane * (182 * 182);
    #pragma unroll
    for (int o = 0; o < 13; o++)
        dst[(size_t)(h0 + o) * 182 + ow] = acc[o];
}

// ---------------------------------------------------------------------------
// Pass 3: conv along D for all 5 fields simultaneously + SSIM + block sums.
// Each thread: 13 outputs at fixed (n, oh, ow). 65 accumulators (unrolled).
// ---------------------------------------------------------------------------
__global__ void __launch_bounds__(256) pass3_kernel() {
    const size_t TOT = (size_t)2 * 14 * 182 * 182;   // 927472
    size_t idx = (size_t)blockIdx.x * blockDim.x + threadIdx.x;
    float lsum = 0.f;
    if (idx < TOT) {
        int ow = (int)(idx % 182); size_t t = idx / 182;
        int oh = (int)(t % 182); t /= 182;
        int strip = (int)(t % 14);
        int n = (int)(t / 14);
        int d0 = strip * 13;
        const float C1 = d_c1c2[0];
        const float C2 = d_c1c2[1];

        float a0[13], a1[13], a2[13], a3[13], a4[13];
        #pragma unroll
        for (int o = 0; o < 13; o++) {
            a0[o] = 0.f; a1[o] = 0.f; a2[o] = 0.f; a3[o] = 0.f; a4[o] = 0.f;
        }
        size_t pbase = (size_t)(n * 192 + d0) * 33124 + (size_t)oh * 182 + ow;
        #pragma unroll
        for (int j = 0; j < 23; j++) {
            size_t p = pbase + (size_t)j * 33124;
            float m1  = d_s2[p];
            float m2  = d_s2[p + FS2];
            float e11 = d_s2[p + 2 * FS2];
            float e22 = d_s2[p + 3 * FS2];
            float e12 = d_s2[p + 4 * FS2];
            #pragma unroll
            for (int o = 0; o < 13; o++) {
                int k = j - o;
                if (k >= 0 && k < WSZ) {
                    float g = c_g[k];
                    a0[o] += g * m1;
                    a1[o] += g * m2;
                    a2[o] += g * e11;
                    a3[o] += g * e22;
                    a4[o] += g * e12;
                }
            }
        }
        #pragma unroll
        for (int o = 0; o < 13; o++) {
            float mu1 = a0[o], mu2 = a1[o];
            float m11 = mu1 * mu1, m22 = mu2 * mu2, m12 = mu1 * mu2;
            float s11 = a2[o] - m11;
            float s22 = a3[o] - m22;
            float s12 = a4[o] - m12;
            float v1 = 2.f * s12 + C2;
            float v2 = s11 + s22 + C2;
            float num = (2.f * m12 + C1) * v1;
            float den = (m11 + m22 + C1) * v2;
            lsum += __fdividef(num, den);
        }
    }
    __shared__ float sred[256];
    sred[threadIdx.x] = lsum;
    __syncthreads();
    #pragma unroll
    for (int off = 128; off; off >>= 1) {
        if (threadIdx.x < off) sred[threadIdx.x] += sred[threadIdx.x + off];
        __syncthreads();
    }
    if (threadIdx.x == 0) d_bsum[blockIdx.x] = sred[0];
}

// Deterministic final reduction over 3623 block sums.
__global__ void final_kernel(float* __restrict__ out) {
    __shared__ double sd[256];
    double s = 0.0;
    for (int i = threadIdx.x; i < 3623; i += 256) s += (double)d_bsum[i];
    sd[threadIdx.x] = s;
    __syncthreads();
    #pragma unroll
    for (int off = 128; off; off >>= 1) {
        if (threadIdx.x < off) sd[threadIdx.x] += sd[threadIdx.x + off];
        __syncthreads();
    }
    if (threadIdx.x == 0)
        out[0] = (float)(sd[0] / 12057136.0);   // 2 * 182^3
}

// ---------------------------------------------------------------------------

extern "C" void kernel_launch(void* const* d_in, const int* in_sizes, int n_in,
                              void* d_out, int out_size) {
    const float* img1 = (const float*)d_in[0];
    const float* img2 = (const float*)d_in[1];
    float* out = (float*)d_out;
    size_t n = (size_t)in_sizes[0];          // 2*192^3

    init_kernel<<<1, 1>>>();
    minmax_kernel<<<512, 256>>>(img1, n);
    const_kernel<<<1, 1>>>();

    pass1_kernel<<<2 * 192 * 192, 192>>>(img1, img2);      // 73728 blocks
    pass2_kernel<<<19110, 256>>>();                        // 5*2*192*14*182 threads
    pass3_kernel<<<3623, 256>>>();                         // 2*14*182*182 threads
    final_kernel<<<1, 256>>>(out);
}